// round 14
// baseline (speedup 1.0000x reference)
#include <cuda_runtime.h>
#include <cuda_fp16.h>
#include <cstdint>
#include <math.h>

#define BATCH 8
#define NTOK 16384
#define MTOT (BATCH * NTOK)   // 131072
#define HGT 128
#define SCALE 0.125f

// ---------------- scratch (device globals) ----------------------------------
__device__ __half g_qh[BATCH * 4 * NTOK * 64];   // (b,h,n,d) fp16, q pre-scaled by 1/8
__device__ __half g_kh[BATCH * 4 * NTOK * 64];
__device__ __half g_vh[BATCH * 4 * NTOK * 64];
__device__ __half g_fh[MTOT * 256];              // fused, fp16
__device__ float g_gl0[BATCH * 64 * 2 * 2];
__device__ float g_gl1[BATCH * 64 * 4 * 4];
__device__ float g_gl2[BATCH * 64 * 8 * 8];
__device__ float g_gl3[BATCH * 64 * 16 * 16];

__device__ __half g_xh[MTOT * 256];
__device__ __half g_wqkv[768 * 256];             // n-major: rows 0-255 q, 256-511 k, 512-767 v
__device__ __half g_wp[256 * 256];

// ---------------- helpers ----------------------------------------------------
__device__ __forceinline__ uint32_t smem_u32(const void* p) {
    uint32_t a;
    asm("{ .reg .u64 t; cvta.to.shared.u64 t, %1; cvt.u32.u64 %0, t; }" : "=r"(a) : "l"(p));
    return a;
}
__device__ __forceinline__ void cp_async16(uint32_t dst, const void* src) {
    asm volatile("cp.async.cg.shared.global [%0], [%1], 16;" :: "r"(dst), "l"(src) : "memory");
}
#define CP_COMMIT() asm volatile("cp.async.commit_group;" ::: "memory")
#define CP_WAIT(n)  asm volatile("cp.async.wait_group %0;" :: "n"(n) : "memory")

__device__ __forceinline__ void ldm_x4(uint32_t* r, uint32_t addr) {
    asm volatile("ldmatrix.sync.aligned.m8n8.x4.shared.b16 {%0,%1,%2,%3}, [%4];"
        : "=r"(r[0]), "=r"(r[1]), "=r"(r[2]), "=r"(r[3]) : "r"(addr));
}
__device__ __forceinline__ void ldm_x4_t(uint32_t* r, uint32_t addr) {
    asm volatile("ldmatrix.sync.aligned.m8n8.x4.trans.shared.b16 {%0,%1,%2,%3}, [%4];"
        : "=r"(r[0]), "=r"(r[1]), "=r"(r[2]), "=r"(r[3]) : "r"(addr));
}
__device__ __forceinline__ void mma16816(float* c, const uint32_t* a, uint32_t b0, uint32_t b1) {
    asm volatile(
        "mma.sync.aligned.m16n8k16.row.col.f32.f16.f16.f32 "
        "{%0,%1,%2,%3}, {%4,%5,%6,%7}, {%8,%9}, {%0,%1,%2,%3};"
        : "+f"(c[0]), "+f"(c[1]), "+f"(c[2]), "+f"(c[3])
        : "r"(a[0]), "r"(a[1]), "r"(a[2]), "r"(a[3]), "r"(b0), "r"(b1));
}
__device__ __forceinline__ uint32_t pack_h2(float a, float b) {
    __half2 h = __floats2half2_rn(a, b);
    return *(uint32_t*)&h;
}

// ---------------- combined weight transpose ----------------------------------
__global__ void wsplit_all(const float* __restrict__ Wq, const float* __restrict__ Wkv,
                           const float* __restrict__ Wp,
                           __half* __restrict__ wqkv, __half* __restrict__ wp)
{
    int i = blockIdx.x * 256 + threadIdx.x;   // over 1024*256
    int k = i & 255, n = i >> 8;
    float w;
    __half* dst;
    if (n < 256)      { w = Wq[(size_t)k * 256 + n];          dst = wqkv + n * 256 + k; }
    else if (n < 768) { w = Wkv[(size_t)k * 512 + (n - 256)]; dst = wqkv + n * 256 + k; }
    else              { w = Wp[(size_t)k * 256 + (n - 768)];  dst = wp + (n - 768) * 256 + k; }
    *dst = __float2half(w);
}

// ---------------- fp32 -> fp16 convert ---------------------------------------
__global__ void conv_fp16(const float* __restrict__ in, __half* __restrict__ h, int n4)
{
    int i = blockIdx.x * 256 + threadIdx.x;
    if (i >= n4) return;
    float4 v = ((const float4*)in)[i];
    ((__half2*)h)[2 * i]     = __floats2half2_rn(v.x, v.y);
    ((__half2*)h)[2 * i + 1] = __floats2half2_rn(v.z, v.w);
}

// ---------------- mma.sync GEMM: (M x 256) @ (256 x NC) ----------------------
// R12-best config: 3-stage cp.async, __launch_bounds__(256,2).
// MODE 0: fused QKV scatter; MODE 2: dense fp32 + bias.
#define RS80 80
#define A_BYTES (128 * RS80)
#define STAGE_BYTES (2 * A_BYTES)             // A + B = 20480
#define GEMM_SMEM (3 * STAGE_BYTES)           // 61440

template <int MODE>
__global__ void __launch_bounds__(256, 2) gemm_mma(
    const __half* __restrict__ A, const __half* __restrict__ B,
    void* out0v, void* out1v, void* out2v, const float* __restrict__ bias)
{
    extern __shared__ char smc[];
    uint32_t smb = smem_u32(smc);
    int tid = threadIdx.x, wid = tid >> 5, lane = tid & 31;
    int warpM = wid & 3, warpN = wid >> 2;
    int rowBase = blockIdx.y * 128;
    int colBase = blockIdx.x * 128;

    const __half* aP = A + (size_t)rowBase * 256;
    const __half* bP = B + (size_t)colBase * 256;

    int r0s = tid >> 2, c0s = tid & 3;
    int r1s = r0s + 64;

    auto issue_stage = [&](int kt, int buf) {
        uint32_t base = smb + buf * STAGE_BYTES;
        size_t src0 = (size_t)r0s * 256 + kt * 32 + c0s * 8;
        size_t src1 = (size_t)r1s * 256 + kt * 32 + c0s * 8;
        uint32_t d0 = base + r0s * RS80 + c0s * 16;
        uint32_t d1 = base + r1s * RS80 + c0s * 16;
        cp_async16(d0, aP + src0);
        cp_async16(d1, aP + src1);
        cp_async16(d0 + A_BYTES, bP + src0);
        cp_async16(d1 + A_BYTES, bP + src1);
        CP_COMMIT();
    };

    float acc[2][8][4];
    #pragma unroll
    for (int mi = 0; mi < 2; mi++)
        #pragma unroll
        for (int ni = 0; ni < 8; ni++)
            #pragma unroll
            for (int j = 0; j < 4; j++) acc[mi][ni][j] = 0.f;

    issue_stage(0, 0);
    issue_stage(1, 1);

    int aRowL = warpM * 32 + (lane & 15);
    int aColL = (lane >> 4) * 16;
    int bRowL = (lane & 7) + ((lane >> 4) & 1) * 8;
    int bColL = ((lane >> 3) & 1) * 16;

    for (int kt = 0; kt < 8; kt++) {
        int buf = kt % 3;
        if (kt < 6) { issue_stage(kt + 2, (kt + 2) % 3); CP_WAIT(2); }
        else if (kt == 6) { CP_WAIT(1); }
        else { CP_WAIT(0); }
        __syncthreads();

        uint32_t sbase = smb + buf * STAGE_BYTES;
        #pragma unroll
        for (int kk = 0; kk < 2; kk++) {
            uint32_t af[2][4];
            uint32_t bfr[4][4];
            #pragma unroll
            for (int mi = 0; mi < 2; mi++)
                ldm_x4(af[mi], sbase + (aRowL + mi * 16) * RS80 + kk * 32 + aColL);
            #pragma unroll
            for (int np = 0; np < 4; np++)
                ldm_x4(bfr[np],
                       sbase + A_BYTES + (warpN * 64 + np * 16 + bRowL) * RS80 + kk * 32 + bColL);
            #pragma unroll
            for (int mi = 0; mi < 2; mi++)
                #pragma unroll
                for (int ni = 0; ni < 8; ni++)
                    mma16816(acc[mi][ni], af[mi],
                             bfr[ni >> 1][(ni & 1) * 2], bfr[ni >> 1][(ni & 1) * 2 + 1]);
        }
        __syncthreads();
    }

    #pragma unroll
    for (int mi = 0; mi < 2; mi++) {
        int r0 = rowBase + warpM * 32 + mi * 16 + (lane >> 2);
        #pragma unroll
        for (int ni = 0; ni < 8; ni++) {
            int c = colBase + warpN * 64 + ni * 8 + (lane & 3) * 2;
            float2 v0 = make_float2(acc[mi][ni][0], acc[mi][ni][1]);
            float2 v1 = make_float2(acc[mi][ni][2], acc[mi][ni][3]);
            if (MODE == 2) {
                float* o = (float*)out0v;
                v0.x += bias[c]; v0.y += bias[c + 1];
                v1.x += bias[c]; v1.y += bias[c + 1];
                *(float2*)(o + (size_t)r0 * 256 + c) = v0;
                *(float2*)(o + (size_t)(r0 + 8) * 256 + c) = v1;
            } else {
                int grp = c >> 8;                 // 0 q, 1 k, 2 v
                int cc = c & 255;
                float s = (grp == 0) ? 0.125f : 1.f;
                __half* basep = (grp == 0) ? (__half*)out0v
                              : (grp == 1) ? (__half*)out1v : (__half*)out2v;
                int h = cc >> 6, d0 = cc & 63;
                int b0i = r0 >> 14, n0 = r0 & 16383;
                int b1i = (r0 + 8) >> 14, n1 = (r0 + 8) & 16383;
                __half2 h0 = __floats2half2_rn(v0.x * s, v0.y * s);
                __half2 h1 = __floats2half2_rn(v1.x * s, v1.y * s);
                *(__half2*)(basep + ((size_t)(b0i * 4 + h) * NTOK + n0) * 64 + d0) = h0;
                *(__half2*)(basep + ((size_t)(b1i * 4 + h) * NTOK + n1) * 64 + d0) = h1;
            }
        }
    }
}

// ---------------- tensor-core attention (heads 2,3 + global) -----------------
template <int S, int MODE>
__global__ void __launch_bounds__(256) attn_tc(
    const __half* __restrict__ qg, const __half* __restrict__ kg,
    const __half* __restrict__ vg, const float* __restrict__ gl16,
    __half* __restrict__ fused, int head)
{
    constexpr int P = (S == 256) ? 16 : 8;
    constexpr int NPX = HGT / P;
    constexpr int KV = (S > 128) ? S : 128;
    constexpr int NBLK = (S == 256) ? 4 : 1;

    extern __shared__ char smc[];
    uint32_t smb = smem_u32(smc);
    const uint32_t qOff = 0, kOff = 128 * 128, vOff = kOff + KV * 128;

    int tid = threadIdx.x, warp = tid >> 5, lane = tid & 31;
    int b = blockIdx.x >> 7;
    int gbase = (blockIdx.x & 127) * 128;
    int gkv = (S == 256) ? (gbase & ~255) : gbase;
    size_t hb = (size_t)(b * 4 + head) * NTOK * 64;

    for (int idx = tid; idx < KV * 8; idx += 256) {
        int row = idx >> 3, c = idx & 7;
        int g = gkv + row;
        int win = g / S, pos = g % S;
        int tok = ((win / NPX) * P + pos / P) * HGT + (win % NPX) * P + pos % P;
        const uint4* ks = (const uint4*)(kg + hb + (size_t)tok * 64) + c;
        const uint4* vs = (const uint4*)(vg + hb + (size_t)tok * 64) + c;
        uint32_t so = row * 128 + ((c ^ (row & 7)) << 4);
        *(uint4*)(smc + kOff + so) = *ks;
        *(uint4*)(smc + vOff + so) = *vs;
    }
    for (int idx = tid; idx < 128 * 8; idx += 256) {
        int row = idx >> 3, c = idx & 7;
        uint32_t so = row * 128 + ((c ^ (row & 7)) << 4);
        if (MODE == 0) {
            int g = gbase + row;
            int win = g / S, pos = g % S;
            int tok = ((win / NPX) * P + pos / P) * HGT + (win % NPX) * P + pos % P;
            *(uint4*)(smc + qOff + so) = *((const uint4*)(qg + hb + (size_t)tok * 64) + c);
        } else {
            int pos = (gbase & 255) + row;
            const float* src = gl16 + (size_t)b * 16384 + pos * 64 + c * 8;
            uint32_t hv[4];
            #pragma unroll
            for (int j = 0; j < 4; j++)
                hv[j] = pack_h2(src[2 * j] * SCALE, src[2 * j + 1] * SCALE);
            *(uint4*)(smc + qOff + so) = *(uint4*)hv;
        }
    }
    __syncthreads();

    int qr = warp * 16;
    uint32_t aq[4][4];
    int arow = qr + (lane & 15);
    #pragma unroll
    for (int kk = 0; kk < 4; kk++)
        ldm_x4(aq[kk], smb + qOff + arow * 128 + (((2 * kk + (lane >> 4)) ^ (lane & 7)) << 4));

    float m0 = -1e30f, m1 = -1e30f, l0 = 0.f, l1 = 0.f;
    float acco[8][4];
    #pragma unroll
    for (int ni = 0; ni < 8; ni++)
        #pragma unroll
        for (int j = 0; j < 4; j++) acco[ni][j] = 0.f;

    int kvBase = (S == 256) ? 0 : (warp >> 2) * 64;
    int brow = (lane & 7) + ((lane >> 4) & 1) * 8;
    int bc = (lane >> 3) & 1;

    for (int blk = 0; blk < NBLK; blk++) {
        int tb = kvBase + blk * 64;
        float accs[8][4];
        #pragma unroll
        for (int ni = 0; ni < 8; ni++)
            #pragma unroll
            for (int j = 0; j < 4; j++) accs[ni][j] = 0.f;

        #pragma unroll
        for (int kk = 0; kk < 4; kk++)
            #pragma unroll
            for (int np = 0; np < 4; np++) {
                int krow = tb + np * 16 + brow;
                uint32_t bf[4];
                ldm_x4(bf, smb + kOff + krow * 128 + (((2 * kk + bc) ^ (lane & 7)) << 4));
                mma16816(accs[np * 2],     aq[kk], bf[0], bf[1]);
                mma16816(accs[np * 2 + 1], aq[kk], bf[2], bf[3]);
            }

        float mx0 = -1e30f, mx1 = -1e30f;
        #pragma unroll
        for (int ni = 0; ni < 8; ni++) {
            mx0 = fmaxf(mx0, fmaxf(accs[ni][0], accs[ni][1]));
            mx1 = fmaxf(mx1, fmaxf(accs[ni][2], accs[ni][3]));
        }
        mx0 = fmaxf(mx0, __shfl_xor_sync(0xffffffff, mx0, 1));
        mx0 = fmaxf(mx0, __shfl_xor_sync(0xffffffff, mx0, 2));
        mx1 = fmaxf(mx1, __shfl_xor_sync(0xffffffff, mx1, 1));
        mx1 = fmaxf(mx1, __shfl_xor_sync(0xffffffff, mx1, 2));
        float mn0 = fmaxf(m0, mx0), mn1 = fmaxf(m1, mx1);
        float f0 = __expf(m0 - mn0), f1 = __expf(m1 - mn1);
        m0 = mn0; m1 = mn1;

        float rs0 = 0.f, rs1 = 0.f;
        uint32_t pf[4][4];
        #pragma unroll
        for (int j = 0; j < 4; j++) {
            float p00 = __expf(accs[2 * j][0] - mn0);
            float p01 = __expf(accs[2 * j][1] - mn0);
            float p02 = __expf(accs[2 * j][2] - mn1);
            float p03 = __expf(accs[2 * j][3] - mn1);
            float p10 = __expf(accs[2 * j + 1][0] - mn0);
            float p11 = __expf(accs[2 * j + 1][1] - mn0);
            float p12 = __expf(accs[2 * j + 1][2] - mn1);
            float p13 = __expf(accs[2 * j + 1][3] - mn1);
            rs0 += (p00 + p01) + (p10 + p11);
            rs1 += (p02 + p03) + (p12 + p13);
            pf[j][0] = pack_h2(p00, p01);
            pf[j][1] = pack_h2(p02, p03);
            pf[j][2] = pack_h2(p10, p11);
            pf[j][3] = pack_h2(p12, p13);
        }
        l0 = l0 * f0 + rs0;
        l1 = l1 * f1 + rs1;
        #pragma unroll
        for (int ni = 0; ni < 8; ni++) {
            acco[ni][0] *= f0; acco[ni][1] *= f0;
            acco[ni][2] *= f1; acco[ni][3] *= f1;
        }

        #pragma unroll
        for (int g = 0; g < 4; g++)
            #pragma unroll
            for (int kk = 0; kk < 4; kk++) {
                int vrow = tb + kk * 16 + brow;
                uint32_t bv[4];
                ldm_x4_t(bv, smb + vOff + vrow * 128 + (((2 * g + bc) ^ (lane & 7)) << 4));
                mma16816(acco[2 * g],     pf[kk], bv[0], bv[2]);
                mma16816(acco[2 * g + 1], pf[kk], bv[1], bv[3]);
            }
    }

    l0 += __shfl_xor_sync(0xffffffff, l0, 1);
    l0 += __shfl_xor_sync(0xffffffff, l0, 2);
    l1 += __shfl_xor_sync(0xffffffff, l1, 1);
    l1 += __shfl_xor_sync(0xffffffff, l1, 2);
    float inv0 = 1.f / l0, inv1 = 1.f / l1;

    int grow0 = gbase + qr + (lane >> 2);
    #pragma unroll
    for (int ni = 0; ni < 8; ni++) {
        int col = head * 64 + ni * 8 + (lane & 3) * 2;
        __half2* d0 = (__half2*)(fused + ((size_t)b * NTOK + grow0) * 256 + col);
        __half2* d1 = (__half2*)(fused + ((size_t)b * NTOK + grow0 + 8) * 256 + col);
        float2 v0 = make_float2(acco[ni][0] * inv0, acco[ni][1] * inv0);
        float2 v1 = make_float2(acco[ni][2] * inv1, acco[ni][3] * inv1);
        if (MODE == 1) {
            float2 o0 = __half22float2(*d0), o1 = __half22float2(*d1);
            v0.x += o0.x; v0.y += o0.y;
            v1.x += o1.x; v1.y += o1.y;
        }
        *d0 = __floats2half2_rn(v0.x, v0.y);
        *d1 = __floats2half2_rn(v1.x, v1.y);
    }
}

// ---------------- smem-staged quad-split attention (heads 0,1) ----------------
// CTA = 256 threads = 64 query-quads = 64 tokens (16 windows for P=2, 4 for P=4).
// K/V converted to fp32 ONCE into smem (68-float stride), then quad-split
// compute reads float4 rows. Same summation order as win_attn_q.
#define WSTRIDE 68

template <int P>
__global__ void __launch_bounds__(256) win_attn_s(
    const __half* __restrict__ qg, const __half* __restrict__ kg,
    const __half* __restrict__ vg, __half* __restrict__ fused, int head)
{
    constexpr int S = P * P;
    constexpr int NPX = HGT / P;
    constexpr int WPB = 64 / S;       // windows per CTA

    __shared__ float Ks[64 * WSTRIDE];
    __shared__ float Vs[64 * WSTRIDE];

    int tid = threadIdx.x;
    int qq = tid >> 2;                // 0..63: query index within CTA
    int part = tid & 3;
    int wl = qq / S, qpos = qq % S;
    int gw0 = blockIdx.x * WPB;
    int b0 = (gw0 + wl) / (NPX * NPX);
    int win0 = (gw0 + wl) % (NPX * NPX);
    size_t hb_q = (size_t)(b0 * 4 + head) * NTOK * 64;

    // stage K/V: 64 tokens x 64 dims, fp32
    for (int idx = tid; idx < 64 * 8; idx += 256) {
        int row = idx >> 3, c = idx & 7;
        int wlr = row / S, posr = row % S;
        int gwr = gw0 + wlr;
        int br = gwr / (NPX * NPX);
        int wr = gwr % (NPX * NPX);
        int tok = ((wr / NPX) * P + posr / P) * HGT + (wr % NPX) * P + posr % P;
        size_t hbr = (size_t)(br * 4 + head) * NTOK * 64;
        uint4 kv4 = *((const uint4*)(kg + hbr + (size_t)tok * 64) + c);
        uint4 vv4 = *((const uint4*)(vg + hbr + (size_t)tok * 64) + c);
        const __half2* kh = (const __half2*)&kv4;
        const __half2* vh = (const __half2*)&vv4;
        float* kd = &Ks[row * WSTRIDE + c * 8];
        float* vd = &Vs[row * WSTRIDE + c * 8];
        #pragma unroll
        for (int j = 0; j < 4; j++) {
            float2 kf = __half22float2(kh[j]);
            float2 vf = __half22float2(vh[j]);
            kd[2 * j] = kf.x; kd[2 * j + 1] = kf.y;
            vd[2 * j] = vf.x; vd[2 * j + 1] = vf.y;
        }
    }

    // q for this thread's query (16 dims)
    int wy = win0 / NPX, wx = win0 % NPX;
    int qtok = (wy * P + qpos / P) * HGT + wx * P + qpos % P;
    float q[16];
    {
        const __half2* qp = (const __half2*)(qg + hb_q + (size_t)qtok * 64 + part * 16);
        #pragma unroll
        for (int j = 0; j < 8; j++) {
            float2 f = __half22float2(qp[j]);
            q[2 * j] = f.x; q[2 * j + 1] = f.y;
        }
    }
    __syncthreads();

    float m = -1e30f, l = 0.f, acc[16];
    #pragma unroll
    for (int j = 0; j < 16; j++) acc[j] = 0.f;

    int krow0 = wl * S;
    #pragma unroll
    for (int k = 0; k < S; k++) {
        const float* kr = &Ks[(krow0 + k) * WSTRIDE + part * 16];
        const float* vr = &Vs[(krow0 + k) * WSTRIDE + part * 16];
        float dp = 0.f;
        #pragma unroll
        for (int j = 0; j < 8; j++)
            dp += q[2 * j] * kr[2 * j] + q[2 * j + 1] * kr[2 * j + 1];
        dp += __shfl_xor_sync(0xffffffff, dp, 1);
        dp += __shfl_xor_sync(0xffffffff, dp, 2);
        if (dp <= m) {
            float p = __expf(dp - m);
            l += p;
            #pragma unroll
            for (int j = 0; j < 16; j++) acc[j] += p * vr[j];
        } else {
            float f = __expf(m - dp);
            m = dp; l = l * f + 1.f;
            #pragma unroll
            for (int j = 0; j < 16; j++) acc[j] = acc[j] * f + vr[j];
        }
    }
    float inv = 1.f / l;
    __half* o = fused + ((size_t)b0 * NTOK + win0 * S + qpos) * 256 + head * 64 + part * 16;
    #pragma unroll
    for (int j = 0; j < 16; j += 2)
        *(__half2*)(o + j) = __floats2half2_rn(acc[j] * inv, acc[j + 1] * inv);
}

// ---------------- block-parallel window mean + bilinear upsample -------------
template <int P>
__global__ void __launch_bounds__(512) mean_red(
    const __half* __restrict__ fused, const float* __restrict__ glp,
    float* __restrict__ glo, int head)
{
    constexpr int S = P * P, NP = (HGT / P) * (HGT / P);
    __shared__ float red[8][64];

    int d = threadIdx.x;
    int wt = threadIdx.y;
    int blk = blockIdx.x;
    int b = blk / (P * P);
    int pos = blk % (P * P);
    int iy = pos / P, ix = pos % P;

    const __half* fp = fused + (size_t)b * NTOK * 256 + (size_t)pos * 256 + head * 64 + d;
    float s = 0.f;
    for (int w = wt; w < NP; w += 8) s += __half2float(fp[(size_t)w * S * 256]);
    red[wt][d] = s;
    __syncthreads();

    if (wt == 0) {
        float tot = red[0][d];
        #pragma unroll
        for (int j = 1; j < 8; j++) tot += red[j][d];
        float val = tot * (1.f / NP);

        if (glp) {
            int Pp = P / 2;
            float sy = (iy + 0.5f) * 0.5f - 0.5f;
            float sx = (ix + 0.5f) * 0.5f - 0.5f;
            float fy = floorf(sy), fx = floorf(sx);
            float wy = sy - fy, wx = sx - fx;
            int y0 = (int)fy, x0 = (int)fx;
            int y0c = max(0, min(Pp - 1, y0)), y1c = max(0, min(Pp - 1, y0 + 1));
            int x0c = max(0, min(Pp - 1, x0)), x1c = max(0, min(Pp - 1, x0 + 1));
            const float* gp = glp + (size_t)(b * 64 + d) * Pp * Pp;
            float v = (1.f - wy) * ((1.f - wx) * gp[y0c * Pp + x0c] + wx * gp[y0c * Pp + x1c])
                    + wy * ((1.f - wx) * gp[y1c * Pp + x0c] + wx * gp[y1c * Pp + x1c]);
            val += v;
        }
        glo[((size_t)(b * 64 + d) * P + iy) * P + ix] = val;
    }
}

// ---------------- launch ------------------------------------------------------
extern "C" void kernel_launch(void* const* d_in, const int* in_sizes, int n_in,
                              void* d_out, int out_size)
{
    (void)in_sizes; (void)n_in; (void)out_size;
    const float* x     = (const float*)d_in[0];
    const float* Wq    = (const float*)d_in[1];
    const float* Wkv   = (const float*)d_in[2];
    const float* Wproj = (const float*)d_in[3];
    const float* bproj = (const float*)d_in[4];
    float* out = (float*)d_out;

    float *gl0, *gl1, *gl2, *gl3;
    __half *qh, *kh, *vh, *fh, *xh, *wqkv, *wp;
    cudaGetSymbolAddress((void**)&qh, g_qh);
    cudaGetSymbolAddress((void**)&kh, g_kh);
    cudaGetSymbolAddress((void**)&vh, g_vh);
    cudaGetSymbolAddress((void**)&fh, g_fh);
    cudaGetSymbolAddress((void**)&gl0, g_gl0);
    cudaGetSymbolAddress((void**)&gl1, g_gl1);
    cudaGetSymbolAddress((void**)&gl2, g_gl2);
    cudaGetSymbolAddress((void**)&gl3, g_gl3);
    cudaGetSymbolAddress((void**)&xh, g_xh);
    cudaGetSymbolAddress((void**)&wqkv, g_wqkv);
    cudaGetSymbolAddress((void**)&wp, g_wp);

    cudaFuncSetAttribute(gemm_mma<0>, cudaFuncAttributeMaxDynamicSharedMemorySize, GEMM_SMEM);
    cudaFuncSetAttribute(gemm_mma<2>, cudaFuncAttributeMaxDynamicSharedMemorySize, GEMM_SMEM);
    cudaFuncSetAttribute((attn_tc<64, 0>),  cudaFuncAttributeMaxDynamicSharedMemorySize, 49152);
    cudaFuncSetAttribute((attn_tc<256, 0>), cudaFuncAttributeMaxDynamicSharedMemorySize, 81920);
    cudaFuncSetAttribute((attn_tc<256, 1>), cudaFuncAttributeMaxDynamicSharedMemorySize, 81920);

    // 1: weights, 2: input convert, 3: fused QKV projection (R12-best path)
    wsplit_all<<<1024, 256>>>(Wq, Wkv, Wproj, wqkv, wp);
    conv_fp16<<<(MTOT * 256 / 4 + 255) / 256, 256>>>(x, xh, MTOT * 256 / 4);
    gemm_mma<0><<<dim3(6, 1024), 256, GEMM_SMEM>>>(xh, wqkv, qh, kh, vh, nullptr);

    // 4 (ncu-profiled slot): smem-staged win_attn_s<4>
    win_attn_s<4><<<2048, 256>>>(qh, kh, vh, fh, 1);
    win_attn_s<2><<<2048, 256>>>(qh, kh, vh, fh, 0);
    attn_tc<64, 0> <<<1024, 256, 49152>>>(qh, kh, vh, nullptr, fh, 2);
    attn_tc<256, 0><<<1024, 256, 81920>>>(qh, kh, vh, nullptr, fh, 3);

    // hierarchical global feature (block-parallel reductions)
    mean_red<2> <<<BATCH * 4,   dim3(64, 8)>>>(fh, nullptr, gl0, 0);
    mean_red<4> <<<BATCH * 16,  dim3(64, 8)>>>(fh, gl0, gl1, 1);
    mean_red<8> <<<BATCH * 64,  dim3(64, 8)>>>(fh, gl1, gl2, 2);
    mean_red<16><<<BATCH * 256, dim3(64, 8)>>>(fh, gl2, gl3, 3);

    // global attention on head 3 (tensor cores, adds into fused)
    attn_tc<256, 1><<<1024, 256, 81920>>>(qh, kh, vh, gl3, fh, 3);

    // output projection (reads fp16 fused directly)
    gemm_mma<2><<<dim3(2, 1024), 256, GEMM_SMEM>>>(fh, wp, out, nullptr, nullptr, bproj);
}

// round 15
// speedup vs baseline: 1.0136x; 1.0136x over previous
#include <cuda_runtime.h>
#include <cuda_fp16.h>
#include <cstdint>
#include <math.h>

#define BATCH 8
#define NTOK 16384
#define MTOT (BATCH * NTOK)   // 131072
#define HGT 128
#define SCALE 0.125f

// ---------------- scratch (device globals) ----------------------------------
__device__ __half g_qh[BATCH * 4 * NTOK * 64];   // (b,h,n,d) fp16, q pre-scaled by 1/8
__device__ __half g_kh[BATCH * 4 * NTOK * 64];
__device__ __half g_vh[BATCH * 4 * NTOK * 64];
__device__ __half g_fh[MTOT * 256];              // fused, fp16
__device__ float g_gl0[BATCH * 64 * 2 * 2];
__device__ float g_gl1[BATCH * 64 * 4 * 4];
__device__ float g_gl2[BATCH * 64 * 8 * 8];
__device__ float g_gl3[BATCH * 64 * 16 * 16];

__device__ __half g_xh[MTOT * 256];
__device__ __half g_wqkv[768 * 256];             // n-major: rows 0-255 q, 256-511 k, 512-767 v
__device__ __half g_wp[256 * 256];

// ---------------- helpers ----------------------------------------------------
__device__ __forceinline__ uint32_t smem_u32(const void* p) {
    uint32_t a;
    asm("{ .reg .u64 t; cvta.to.shared.u64 t, %1; cvt.u32.u64 %0, t; }" : "=r"(a) : "l"(p));
    return a;
}
__device__ __forceinline__ void cp_async16(uint32_t dst, const void* src) {
    asm volatile("cp.async.cg.shared.global [%0], [%1], 16;" :: "r"(dst), "l"(src) : "memory");
}
#define CP_COMMIT() asm volatile("cp.async.commit_group;" ::: "memory")
#define CP_WAIT(n)  asm volatile("cp.async.wait_group %0;" :: "n"(n) : "memory")

__device__ __forceinline__ void ldm_x4(uint32_t* r, uint32_t addr) {
    asm volatile("ldmatrix.sync.aligned.m8n8.x4.shared.b16 {%0,%1,%2,%3}, [%4];"
        : "=r"(r[0]), "=r"(r[1]), "=r"(r[2]), "=r"(r[3]) : "r"(addr));
}
__device__ __forceinline__ void ldm_x4_t(uint32_t* r, uint32_t addr) {
    asm volatile("ldmatrix.sync.aligned.m8n8.x4.trans.shared.b16 {%0,%1,%2,%3}, [%4];"
        : "=r"(r[0]), "=r"(r[1]), "=r"(r[2]), "=r"(r[3]) : "r"(addr));
}
__device__ __forceinline__ void mma16816(float* c, const uint32_t* a, uint32_t b0, uint32_t b1) {
    asm volatile(
        "mma.sync.aligned.m16n8k16.row.col.f32.f16.f16.f32 "
        "{%0,%1,%2,%3}, {%4,%5,%6,%7}, {%8,%9}, {%0,%1,%2,%3};"
        : "+f"(c[0]), "+f"(c[1]), "+f"(c[2]), "+f"(c[3])
        : "r"(a[0]), "r"(a[1]), "r"(a[2]), "r"(a[3]), "r"(b0), "r"(b1));
}
__device__ __forceinline__ uint32_t pack_h2(float a, float b) {
    __half2 h = __floats2half2_rn(a, b);
    return *(uint32_t*)&h;
}

// ---------------- combined weight transpose ----------------------------------
__global__ void wsplit_all(const float* __restrict__ Wq, const float* __restrict__ Wkv,
                           const float* __restrict__ Wp,
                           __half* __restrict__ wqkv, __half* __restrict__ wp)
{
    int i = blockIdx.x * 256 + threadIdx.x;   // over 1024*256
    int k = i & 255, n = i >> 8;
    float w;
    __half* dst;
    if (n < 256)      { w = Wq[(size_t)k * 256 + n];          dst = wqkv + n * 256 + k; }
    else if (n < 768) { w = Wkv[(size_t)k * 512 + (n - 256)]; dst = wqkv + n * 256 + k; }
    else              { w = Wp[(size_t)k * 256 + (n - 768)];  dst = wp + (n - 768) * 256 + k; }
    *dst = __float2half(w);
}

// ---------------- fp32 -> fp16 convert ---------------------------------------
__global__ void conv_fp16(const float* __restrict__ in, __half* __restrict__ h, int n4)
{
    int i = blockIdx.x * 256 + threadIdx.x;
    if (i >= n4) return;
    float4 v = ((const float4*)in)[i];
    ((__half2*)h)[2 * i]     = __floats2half2_rn(v.x, v.y);
    ((__half2*)h)[2 * i + 1] = __floats2half2_rn(v.z, v.w);
}

// ---------------- mma.sync GEMM: (M x 256) @ (256 x NC) ----------------------
// R12-best config: 3-stage cp.async, __launch_bounds__(256,2).
#define RS80 80
#define A_BYTES (128 * RS80)
#define STAGE_BYTES (2 * A_BYTES)             // A + B = 20480
#define GEMM_SMEM (3 * STAGE_BYTES)           // 61440

template <int MODE>
__global__ void __launch_bounds__(256, 2) gemm_mma(
    const __half* __restrict__ A, const __half* __restrict__ B,
    void* out0v, void* out1v, void* out2v, const float* __restrict__ bias)
{
    extern __shared__ char smc[];
    uint32_t smb = smem_u32(smc);
    int tid = threadIdx.x, wid = tid >> 5, lane = tid & 31;
    int warpM = wid & 3, warpN = wid >> 2;
    int rowBase = blockIdx.y * 128;
    int colBase = blockIdx.x * 128;

    const __half* aP = A + (size_t)rowBase * 256;
    const __half* bP = B + (size_t)colBase * 256;

    int r0s = tid >> 2, c0s = tid & 3;
    int r1s = r0s + 64;

    auto issue_stage = [&](int kt, int buf) {
        uint32_t base = smb + buf * STAGE_BYTES;
        size_t src0 = (size_t)r0s * 256 + kt * 32 + c0s * 8;
        size_t src1 = (size_t)r1s * 256 + kt * 32 + c0s * 8;
        uint32_t d0 = base + r0s * RS80 + c0s * 16;
        uint32_t d1 = base + r1s * RS80 + c0s * 16;
        cp_async16(d0, aP + src0);
        cp_async16(d1, aP + src1);
        cp_async16(d0 + A_BYTES, bP + src0);
        cp_async16(d1 + A_BYTES, bP + src1);
        CP_COMMIT();
    };

    float acc[2][8][4];
    #pragma unroll
    for (int mi = 0; mi < 2; mi++)
        #pragma unroll
        for (int ni = 0; ni < 8; ni++)
            #pragma unroll
            for (int j = 0; j < 4; j++) acc[mi][ni][j] = 0.f;

    issue_stage(0, 0);
    issue_stage(1, 1);

    int aRowL = warpM * 32 + (lane & 15);
    int aColL = (lane >> 4) * 16;
    int bRowL = (lane & 7) + ((lane >> 4) & 1) * 8;
    int bColL = ((lane >> 3) & 1) * 16;

    for (int kt = 0; kt < 8; kt++) {
        int buf = kt % 3;
        if (kt < 6) { issue_stage(kt + 2, (kt + 2) % 3); CP_WAIT(2); }
        else if (kt == 6) { CP_WAIT(1); }
        else { CP_WAIT(0); }
        __syncthreads();

        uint32_t sbase = smb + buf * STAGE_BYTES;
        #pragma unroll
        for (int kk = 0; kk < 2; kk++) {
            uint32_t af[2][4];
            uint32_t bfr[4][4];
            #pragma unroll
            for (int mi = 0; mi < 2; mi++)
                ldm_x4(af[mi], sbase + (aRowL + mi * 16) * RS80 + kk * 32 + aColL);
            #pragma unroll
            for (int np = 0; np < 4; np++)
                ldm_x4(bfr[np],
                       sbase + A_BYTES + (warpN * 64 + np * 16 + bRowL) * RS80 + kk * 32 + bColL);
            #pragma unroll
            for (int mi = 0; mi < 2; mi++)
                #pragma unroll
                for (int ni = 0; ni < 8; ni++)
                    mma16816(acc[mi][ni], af[mi],
                             bfr[ni >> 1][(ni & 1) * 2], bfr[ni >> 1][(ni & 1) * 2 + 1]);
        }
        __syncthreads();
    }

    #pragma unroll
    for (int mi = 0; mi < 2; mi++) {
        int r0 = rowBase + warpM * 32 + mi * 16 + (lane >> 2);
        #pragma unroll
        for (int ni = 0; ni < 8; ni++) {
            int c = colBase + warpN * 64 + ni * 8 + (lane & 3) * 2;
            float2 v0 = make_float2(acc[mi][ni][0], acc[mi][ni][1]);
            float2 v1 = make_float2(acc[mi][ni][2], acc[mi][ni][3]);
            if (MODE == 2) {
                float* o = (float*)out0v;
                v0.x += bias[c]; v0.y += bias[c + 1];
                v1.x += bias[c]; v1.y += bias[c + 1];
                *(float2*)(o + (size_t)r0 * 256 + c) = v0;
                *(float2*)(o + (size_t)(r0 + 8) * 256 + c) = v1;
            } else {
                int grp = c >> 8;                 // 0 q, 1 k, 2 v
                int cc = c & 255;
                float s = (grp == 0) ? 0.125f : 1.f;
                __half* basep = (grp == 0) ? (__half*)out0v
                              : (grp == 1) ? (__half*)out1v : (__half*)out2v;
                int h = cc >> 6, d0 = cc & 63;
                int b0i = r0 >> 14, n0 = r0 & 16383;
                int b1i = (r0 + 8) >> 14, n1 = (r0 + 8) & 16383;
                __half2 h0 = __floats2half2_rn(v0.x * s, v0.y * s);
                __half2 h1 = __floats2half2_rn(v1.x * s, v1.y * s);
                *(__half2*)(basep + ((size_t)(b0i * 4 + h) * NTOK + n0) * 64 + d0) = h0;
                *(__half2*)(basep + ((size_t)(b1i * 4 + h) * NTOK + n1) * 64 + d0) = h1;
            }
        }
    }
}

// ---------------- tensor-core attention (heads 2,3 + global) -----------------
template <int S, int MODE>
__global__ void __launch_bounds__(256) attn_tc(
    const __half* __restrict__ qg, const __half* __restrict__ kg,
    const __half* __restrict__ vg, const float* __restrict__ gl16,
    __half* __restrict__ fused, int head)
{
    constexpr int P = (S == 256) ? 16 : 8;
    constexpr int NPX = HGT / P;
    constexpr int KV = (S > 128) ? S : 128;
    constexpr int NBLK = (S == 256) ? 4 : 1;

    extern __shared__ char smc[];
    uint32_t smb = smem_u32(smc);
    const uint32_t qOff = 0, kOff = 128 * 128, vOff = kOff + KV * 128;

    int tid = threadIdx.x, warp = tid >> 5, lane = tid & 31;
    int b = blockIdx.x >> 7;
    int gbase = (blockIdx.x & 127) * 128;
    int gkv = (S == 256) ? (gbase & ~255) : gbase;
    size_t hb = (size_t)(b * 4 + head) * NTOK * 64;

    for (int idx = tid; idx < KV * 8; idx += 256) {
        int row = idx >> 3, c = idx & 7;
        int g = gkv + row;
        int win = g / S, pos = g % S;
        int tok = ((win / NPX) * P + pos / P) * HGT + (win % NPX) * P + pos % P;
        const uint4* ks = (const uint4*)(kg + hb + (size_t)tok * 64) + c;
        const uint4* vs = (const uint4*)(vg + hb + (size_t)tok * 64) + c;
        uint32_t so = row * 128 + ((c ^ (row & 7)) << 4);
        *(uint4*)(smc + kOff + so) = *ks;
        *(uint4*)(smc + vOff + so) = *vs;
    }
    for (int idx = tid; idx < 128 * 8; idx += 256) {
        int row = idx >> 3, c = idx & 7;
        uint32_t so = row * 128 + ((c ^ (row & 7)) << 4);
        if (MODE == 0) {
            int g = gbase + row;
            int win = g / S, pos = g % S;
            int tok = ((win / NPX) * P + pos / P) * HGT + (win % NPX) * P + pos % P;
            *(uint4*)(smc + qOff + so) = *((const uint4*)(qg + hb + (size_t)tok * 64) + c);
        } else {
            int pos = (gbase & 255) + row;
            const float* src = gl16 + (size_t)b * 16384 + pos * 64 + c * 8;
            uint32_t hv[4];
            #pragma unroll
            for (int j = 0; j < 4; j++)
                hv[j] = pack_h2(src[2 * j] * SCALE, src[2 * j + 1] * SCALE);
            *(uint4*)(smc + qOff + so) = *(uint4*)hv;
        }
    }
    __syncthreads();

    int qr = warp * 16;
    uint32_t aq[4][4];
    int arow = qr + (lane & 15);
    #pragma unroll
    for (int kk = 0; kk < 4; kk++)
        ldm_x4(aq[kk], smb + qOff + arow * 128 + (((2 * kk + (lane >> 4)) ^ (lane & 7)) << 4));

    float m0 = -1e30f, m1 = -1e30f, l0 = 0.f, l1 = 0.f;
    float acco[8][4];
    #pragma unroll
    for (int ni = 0; ni < 8; ni++)
        #pragma unroll
        for (int j = 0; j < 4; j++) acco[ni][j] = 0.f;

    int kvBase = (S == 256) ? 0 : (warp >> 2) * 64;
    int brow = (lane & 7) + ((lane >> 4) & 1) * 8;
    int bc = (lane >> 3) & 1;

    for (int blk = 0; blk < NBLK; blk++) {
        int tb = kvBase + blk * 64;
        float accs[8][4];
        #pragma unroll
        for (int ni = 0; ni < 8; ni++)
            #pragma unroll
            for (int j = 0; j < 4; j++) accs[ni][j] = 0.f;

        #pragma unroll
        for (int kk = 0; kk < 4; kk++)
            #pragma unroll
            for (int np = 0; np < 4; np++) {
                int krow = tb + np * 16 + brow;
                uint32_t bf[4];
                ldm_x4(bf, smb + kOff + krow * 128 + (((2 * kk + bc) ^ (lane & 7)) << 4));
                mma16816(accs[np * 2],     aq[kk], bf[0], bf[1]);
                mma16816(accs[np * 2 + 1], aq[kk], bf[2], bf[3]);
            }

        float mx0 = -1e30f, mx1 = -1e30f;
        #pragma unroll
        for (int ni = 0; ni < 8; ni++) {
            mx0 = fmaxf(mx0, fmaxf(accs[ni][0], accs[ni][1]));
            mx1 = fmaxf(mx1, fmaxf(accs[ni][2], accs[ni][3]));
        }
        mx0 = fmaxf(mx0, __shfl_xor_sync(0xffffffff, mx0, 1));
        mx0 = fmaxf(mx0, __shfl_xor_sync(0xffffffff, mx0, 2));
        mx1 = fmaxf(mx1, __shfl_xor_sync(0xffffffff, mx1, 1));
        mx1 = fmaxf(mx1, __shfl_xor_sync(0xffffffff, mx1, 2));
        float mn0 = fmaxf(m0, mx0), mn1 = fmaxf(m1, mx1);
        float f0 = __expf(m0 - mn0), f1 = __expf(m1 - mn1);
        m0 = mn0; m1 = mn1;

        float rs0 = 0.f, rs1 = 0.f;
        uint32_t pf[4][4];
        #pragma unroll
        for (int j = 0; j < 4; j++) {
            float p00 = __expf(accs[2 * j][0] - mn0);
            float p01 = __expf(accs[2 * j][1] - mn0);
            float p02 = __expf(accs[2 * j][2] - mn1);
            float p03 = __expf(accs[2 * j][3] - mn1);
            float p10 = __expf(accs[2 * j + 1][0] - mn0);
            float p11 = __expf(accs[2 * j + 1][1] - mn0);
            float p12 = __expf(accs[2 * j + 1][2] - mn1);
            float p13 = __expf(accs[2 * j + 1][3] - mn1);
            rs0 += (p00 + p01) + (p10 + p11);
            rs1 += (p02 + p03) + (p12 + p13);
            pf[j][0] = pack_h2(p00, p01);
            pf[j][1] = pack_h2(p02, p03);
            pf[j][2] = pack_h2(p10, p11);
            pf[j][3] = pack_h2(p12, p13);
        }
        l0 = l0 * f0 + rs0;
        l1 = l1 * f1 + rs1;
        #pragma unroll
        for (int ni = 0; ni < 8; ni++) {
            acco[ni][0] *= f0; acco[ni][1] *= f0;
            acco[ni][2] *= f1; acco[ni][3] *= f1;
        }

        #pragma unroll
        for (int g = 0; g < 4; g++)
            #pragma unroll
            for (int kk = 0; kk < 4; kk++) {
                int vrow = tb + kk * 16 + brow;
                uint32_t bv[4];
                ldm_x4_t(bv, smb + vOff + vrow * 128 + (((2 * g + bc) ^ (lane & 7)) << 4));
                mma16816(acco[2 * g],     pf[kk], bv[0], bv[2]);
                mma16816(acco[2 * g + 1], pf[kk], bv[1], bv[3]);
            }
    }

    l0 += __shfl_xor_sync(0xffffffff, l0, 1);
    l0 += __shfl_xor_sync(0xffffffff, l0, 2);
    l1 += __shfl_xor_sync(0xffffffff, l1, 1);
    l1 += __shfl_xor_sync(0xffffffff, l1, 2);
    float inv0 = 1.f / l0, inv1 = 1.f / l1;

    int grow0 = gbase + qr + (lane >> 2);
    #pragma unroll
    for (int ni = 0; ni < 8; ni++) {
        int col = head * 64 + ni * 8 + (lane & 3) * 2;
        __half2* d0 = (__half2*)(fused + ((size_t)b * NTOK + grow0) * 256 + col);
        __half2* d1 = (__half2*)(fused + ((size_t)b * NTOK + grow0 + 8) * 256 + col);
        float2 v0 = make_float2(acco[ni][0] * inv0, acco[ni][1] * inv0);
        float2 v1 = make_float2(acco[ni][2] * inv1, acco[ni][3] * inv1);
        if (MODE == 1) {
            float2 o0 = __half22float2(*d0), o1 = __half22float2(*d1);
            v0.x += o0.x; v0.y += o0.y;
            v1.x += o1.x; v1.y += o1.y;
        }
        *d0 = __floats2half2_rn(v0.x, v0.y);
        *d1 = __floats2half2_rn(v1.x, v1.y);
    }
}

// ---------------- smem-staged quad-split attention (heads 0,1) ----------------
// Vectorized: float4 LDS reads (R14's scalar LDS saturated the smem pipe at
// L1=89.5%). Same staging, same summation order.
#define WSTRIDE 68

template <int P>
__global__ void __launch_bounds__(256) win_attn_s(
    const __half* __restrict__ qg, const __half* __restrict__ kg,
    const __half* __restrict__ vg, __half* __restrict__ fused, int head)
{
    constexpr int S = P * P;
    constexpr int NPX = HGT / P;
    constexpr int WPB = 64 / S;       // windows per CTA

    __shared__ float Ks[64 * WSTRIDE];
    __shared__ float Vs[64 * WSTRIDE];

    int tid = threadIdx.x;
    int qq = tid >> 2;                // 0..63
    int part = tid & 3;
    int wl = qq / S, qpos = qq % S;
    int gw0 = blockIdx.x * WPB;
    int b0 = (gw0 + wl) / (NPX * NPX);
    int win0 = (gw0 + wl) % (NPX * NPX);
    size_t hb_q = (size_t)(b0 * 4 + head) * NTOK * 64;

    // stage K/V: 64 tokens x 64 dims, fp32
    for (int idx = tid; idx < 64 * 8; idx += 256) {
        int row = idx >> 3, c = idx & 7;
        int wlr = row / S, posr = row % S;
        int gwr = gw0 + wlr;
        int br = gwr / (NPX * NPX);
        int wr = gwr % (NPX * NPX);
        int tok = ((wr / NPX) * P + posr / P) * HGT + (wr % NPX) * P + posr % P;
        size_t hbr = (size_t)(br * 4 + head) * NTOK * 64;
        uint4 kv4 = *((const uint4*)(kg + hbr + (size_t)tok * 64) + c);
        uint4 vv4 = *((const uint4*)(vg + hbr + (size_t)tok * 64) + c);
        const __half2* kh = (const __half2*)&kv4;
        const __half2* vh = (const __half2*)&vv4;
        float* kd = &Ks[row * WSTRIDE + c * 8];
        float* vd = &Vs[row * WSTRIDE + c * 8];
        #pragma unroll
        for (int j = 0; j < 4; j++) {
            float2 kf = __half22float2(kh[j]);
            float2 vf = __half22float2(vh[j]);
            kd[2 * j] = kf.x; kd[2 * j + 1] = kf.y;
            vd[2 * j] = vf.x; vd[2 * j + 1] = vf.y;
        }
    }

    // q for this thread's query (16 dims)
    int wy = win0 / NPX, wx = win0 % NPX;
    int qtok = (wy * P + qpos / P) * HGT + wx * P + qpos % P;
    float q[16];
    {
        const __half2* qp = (const __half2*)(qg + hb_q + (size_t)qtok * 64 + part * 16);
        #pragma unroll
        for (int j = 0; j < 8; j++) {
            float2 f = __half22float2(qp[j]);
            q[2 * j] = f.x; q[2 * j + 1] = f.y;
        }
    }
    __syncthreads();

    float m = -1e30f, l = 0.f, acc[16];
    #pragma unroll
    for (int j = 0; j < 16; j++) acc[j] = 0.f;

    int krow0 = wl * S;
    #pragma unroll
    for (int k = 0; k < S; k++) {
        const float4* kr = (const float4*)&Ks[(krow0 + k) * WSTRIDE + part * 16];
        const float4* vr = (const float4*)&Vs[(krow0 + k) * WSTRIDE + part * 16];
        float4 k4[4] = { kr[0], kr[1], kr[2], kr[3] };
        float4 v4[4] = { vr[0], vr[1], vr[2], vr[3] };
        const float* kf = (const float*)k4;
        const float* vf = (const float*)v4;
        float dp = 0.f;
        #pragma unroll
        for (int j = 0; j < 8; j++)
            dp += q[2 * j] * kf[2 * j] + q[2 * j + 1] * kf[2 * j + 1];
        dp += __shfl_xor_sync(0xffffffff, dp, 1);
        dp += __shfl_xor_sync(0xffffffff, dp, 2);
        if (dp <= m) {
            float p = __expf(dp - m);
            l += p;
            #pragma unroll
            for (int j = 0; j < 16; j++) acc[j] += p * vf[j];
        } else {
            float f = __expf(m - dp);
            m = dp; l = l * f + 1.f;
            #pragma unroll
            for (int j = 0; j < 16; j++) acc[j] = acc[j] * f + vf[j];
        }
    }
    float inv = 1.f / l;
    __half* o = fused + ((size_t)b0 * NTOK + win0 * S + qpos) * 256 + head * 64 + part * 16;
    #pragma unroll
    for (int j = 0; j < 16; j += 2)
        *(__half2*)(o + j) = __floats2half2_rn(acc[j] * inv, acc[j + 1] * inv);
}

// ---------------- block-parallel window mean + bilinear upsample -------------
template <int P>
__global__ void __launch_bounds__(512) mean_red(
    const __half* __restrict__ fused, const float* __restrict__ glp,
    float* __restrict__ glo, int head)
{
    constexpr int S = P * P, NP = (HGT / P) * (HGT / P);
    __shared__ float red[8][64];

    int d = threadIdx.x;
    int wt = threadIdx.y;
    int blk = blockIdx.x;
    int b = blk / (P * P);
    int pos = blk % (P * P);
    int iy = pos / P, ix = pos % P;

    const __half* fp = fused + (size_t)b * NTOK * 256 + (size_t)pos * 256 + head * 64 + d;
    float s = 0.f;
    for (int w = wt; w < NP; w += 8) s += __half2float(fp[(size_t)w * S * 256]);
    red[wt][d] = s;
    __syncthreads();

    if (wt == 0) {
        float tot = red[0][d];
        #pragma unroll
        for (int j = 1; j < 8; j++) tot += red[j][d];
        float val = tot * (1.f / NP);

        if (glp) {
            int Pp = P / 2;
            float sy = (iy + 0.5f) * 0.5f - 0.5f;
            float sx = (ix + 0.5f) * 0.5f - 0.5f;
            float fy = floorf(sy), fx = floorf(sx);
            float wy = sy - fy, wx = sx - fx;
            int y0 = (int)fy, x0 = (int)fx;
            int y0c = max(0, min(Pp - 1, y0)), y1c = max(0, min(Pp - 1, y0 + 1));
            int x0c = max(0, min(Pp - 1, x0)), x1c = max(0, min(Pp - 1, x0 + 1));
            const float* gp = glp + (size_t)(b * 64 + d) * Pp * Pp;
            float v = (1.f - wy) * ((1.f - wx) * gp[y0c * Pp + x0c] + wx * gp[y0c * Pp + x1c])
                    + wy * ((1.f - wx) * gp[y1c * Pp + x0c] + wx * gp[y1c * Pp + x1c]);
            val += v;
        }
        glo[((size_t)(b * 64 + d) * P + iy) * P + ix] = val;
    }
}

// ---------------- launch ------------------------------------------------------
extern "C" void kernel_launch(void* const* d_in, const int* in_sizes, int n_in,
                              void* d_out, int out_size)
{
    (void)in_sizes; (void)n_in; (void)out_size;
    const float* x     = (const float*)d_in[0];
    const float* Wq    = (const float*)d_in[1];
    const float* Wkv   = (const float*)d_in[2];
    const float* Wproj = (const float*)d_in[3];
    const float* bproj = (const float*)d_in[4];
    float* out = (float*)d_out;

    float *gl0, *gl1, *gl2, *gl3;
    __half *qh, *kh, *vh, *fh, *xh, *wqkv, *wp;
    cudaGetSymbolAddress((void**)&qh, g_qh);
    cudaGetSymbolAddress((void**)&kh, g_kh);
    cudaGetSymbolAddress((void**)&vh, g_vh);
    cudaGetSymbolAddress((void**)&fh, g_fh);
    cudaGetSymbolAddress((void**)&gl0, g_gl0);
    cudaGetSymbolAddress((void**)&gl1, g_gl1);
    cudaGetSymbolAddress((void**)&gl2, g_gl2);
    cudaGetSymbolAddress((void**)&gl3, g_gl3);
    cudaGetSymbolAddress((void**)&xh, g_xh);
    cudaGetSymbolAddress((void**)&wqkv, g_wqkv);
    cudaGetSymbolAddress((void**)&wp, g_wp);

    cudaFuncSetAttribute(gemm_mma<0>, cudaFuncAttributeMaxDynamicSharedMemorySize, GEMM_SMEM);
    cudaFuncSetAttribute(gemm_mma<2>, cudaFuncAttributeMaxDynamicSharedMemorySize, GEMM_SMEM);
    cudaFuncSetAttribute((attn_tc<64, 0>),  cudaFuncAttributeMaxDynamicSharedMemorySize, 49152);
    cudaFuncSetAttribute((attn_tc<256, 0>), cudaFuncAttributeMaxDynamicSharedMemorySize, 81920);
    cudaFuncSetAttribute((attn_tc<256, 1>), cudaFuncAttributeMaxDynamicSharedMemorySize, 81920);

    // 1: weights, 2: input convert, 3: fused QKV projection
    wsplit_all<<<1024, 256>>>(Wq, Wkv, Wproj, wqkv, wp);
    conv_fp16<<<(MTOT * 256 / 4 + 255) / 256, 256>>>(x, xh, MTOT * 256 / 4);
    gemm_mma<0><<<dim3(6, 1024), 256, GEMM_SMEM>>>(xh, wqkv, qh, kh, vh, nullptr);

    // 4 (ncu-profiled slot): vectorized win_attn_s<4>
    win_attn_s<4><<<2048, 256>>>(qh, kh, vh, fh, 1);
    win_attn_s<2><<<2048, 256>>>(qh, kh, vh, fh, 0);
    attn_tc<64, 0> <<<1024, 256, 49152>>>(qh, kh, vh, nullptr, fh, 2);
    attn_tc<256, 0><<<1024, 256, 81920>>>(qh, kh, vh, nullptr, fh, 3);

    // hierarchical global feature (block-parallel reductions)
    mean_red<2> <<<BATCH * 4,   dim3(64, 8)>>>(fh, nullptr, gl0, 0);
    mean_red<4> <<<BATCH * 16,  dim3(64, 8)>>>(fh, gl0, gl1, 1);
    mean_red<8> <<<BATCH * 64,  dim3(64, 8)>>>(fh, gl1, gl2, 2);
    mean_red<16><<<BATCH * 256, dim3(64, 8)>>>(fh, gl2, gl3, 3);

    // global attention on head 3 (tensor cores, adds into fused)
    attn_tc<256, 1><<<1024, 256, 81920>>>(qh, kh, vh, gl3, fh, 3);

    // output projection (reads fp16 fused directly)
    gemm_mma<2><<<dim3(2, 1024), 256, GEMM_SMEM>>>(fh, wp, out, nullptr, nullptr, bproj);
}

// round 16
// speedup vs baseline: 1.1326x; 1.1175x over previous
#include <cuda_runtime.h>
#include <cuda_fp16.h>
#include <cstdint>
#include <math.h>

#define BATCH 8
#define NTOK 16384
#define MTOT (BATCH * NTOK)   // 131072
#define HGT 128
#define SCALE 0.125f

// ---------------- scratch (device globals) ----------------------------------
__device__ __half g_qh[BATCH * 4 * NTOK * 64];   // (b,h,n,d) fp16, q pre-scaled by 1/8
__device__ __half g_kh[BATCH * 4 * NTOK * 64];
__device__ __half g_vh[BATCH * 4 * NTOK * 64];
__device__ __half g_fh[MTOT * 256];              // fused, fp16
__device__ float g_gl0[BATCH * 64 * 2 * 2];
__device__ float g_gl1[BATCH * 64 * 4 * 4];
__device__ float g_gl2[BATCH * 64 * 8 * 8];
__device__ float g_gl3[BATCH * 64 * 16 * 16];

__device__ __half g_xh[MTOT * 256];
__device__ __half g_wqkv[768 * 256];             // n-major: rows 0-255 q, 256-511 k, 512-767 v
__device__ __half g_wp[256 * 256];

// ---------------- helpers ----------------------------------------------------
__device__ __forceinline__ uint32_t smem_u32(const void* p) {
    uint32_t a;
    asm("{ .reg .u64 t; cvta.to.shared.u64 t, %1; cvt.u32.u64 %0, t; }" : "=r"(a) : "l"(p));
    return a;
}
__device__ __forceinline__ void cp_async16(uint32_t dst, const void* src) {
    asm volatile("cp.async.cg.shared.global [%0], [%1], 16;" :: "r"(dst), "l"(src) : "memory");
}
#define CP_COMMIT() asm volatile("cp.async.commit_group;" ::: "memory")
#define CP_WAIT(n)  asm volatile("cp.async.wait_group %0;" :: "n"(n) : "memory")

__device__ __forceinline__ void ldm_x4(uint32_t* r, uint32_t addr) {
    asm volatile("ldmatrix.sync.aligned.m8n8.x4.shared.b16 {%0,%1,%2,%3}, [%4];"
        : "=r"(r[0]), "=r"(r[1]), "=r"(r[2]), "=r"(r[3]) : "r"(addr));
}
__device__ __forceinline__ void ldm_x4_t(uint32_t* r, uint32_t addr) {
    asm volatile("ldmatrix.sync.aligned.m8n8.x4.trans.shared.b16 {%0,%1,%2,%3}, [%4];"
        : "=r"(r[0]), "=r"(r[1]), "=r"(r[2]), "=r"(r[3]) : "r"(addr));
}
__device__ __forceinline__ void mma16816(float* c, const uint32_t* a, uint32_t b0, uint32_t b1) {
    asm volatile(
        "mma.sync.aligned.m16n8k16.row.col.f32.f16.f16.f32 "
        "{%0,%1,%2,%3}, {%4,%5,%6,%7}, {%8,%9}, {%0,%1,%2,%3};"
        : "+f"(c[0]), "+f"(c[1]), "+f"(c[2]), "+f"(c[3])
        : "r"(a[0]), "r"(a[1]), "r"(a[2]), "r"(a[3]), "r"(b0), "r"(b1));
}
__device__ __forceinline__ uint32_t pack_h2(float a, float b) {
    __half2 h = __floats2half2_rn(a, b);
    return *(uint32_t*)&h;
}

// ---------------- combined weight transpose ----------------------------------
__global__ void wsplit_all(const float* __restrict__ Wq, const float* __restrict__ Wkv,
                           const float* __restrict__ Wp,
                           __half* __restrict__ wqkv, __half* __restrict__ wp)
{
    int i = blockIdx.x * 256 + threadIdx.x;   // over 1024*256
    int k = i & 255, n = i >> 8;
    float w;
    __half* dst;
    if (n < 256)      { w = Wq[(size_t)k * 256 + n];          dst = wqkv + n * 256 + k; }
    else if (n < 768) { w = Wkv[(size_t)k * 512 + (n - 256)]; dst = wqkv + n * 256 + k; }
    else              { w = Wp[(size_t)k * 256 + (n - 768)];  dst = wp + (n - 768) * 256 + k; }
    *dst = __float2half(w);
}

// ---------------- fp32 -> fp16 convert ---------------------------------------
__global__ void conv_fp16(const float* __restrict__ in, __half* __restrict__ h, int n4)
{
    int i = blockIdx.x * 256 + threadIdx.x;
    if (i >= n4) return;
    float4 v = ((const float4*)in)[i];
    ((__half2*)h)[2 * i]     = __floats2half2_rn(v.x, v.y);
    ((__half2*)h)[2 * i + 1] = __floats2half2_rn(v.z, v.w);
}

// ---------------- mma.sync GEMM: (M x 256) @ (256 x NC) ----------------------
// R12-best config: 3-stage cp.async, __launch_bounds__(256,2).
#define RS80 80
#define A_BYTES (128 * RS80)
#define STAGE_BYTES (2 * A_BYTES)             // A + B = 20480
#define GEMM_SMEM (3 * STAGE_BYTES)           // 61440

template <int MODE>
__global__ void __launch_bounds__(256, 2) gemm_mma(
    const __half* __restrict__ A, const __half* __restrict__ B,
    void* out0v, void* out1v, void* out2v, const float* __restrict__ bias)
{
    extern __shared__ char smc[];
    uint32_t smb = smem_u32(smc);
    int tid = threadIdx.x, wid = tid >> 5, lane = tid & 31;
    int warpM = wid & 3, warpN = wid >> 2;
    int rowBase = blockIdx.y * 128;
    int colBase = blockIdx.x * 128;

    const __half* aP = A + (size_t)rowBase * 256;
    const __half* bP = B + (size_t)colBase * 256;

    int r0s = tid >> 2, c0s = tid & 3;
    int r1s = r0s + 64;

    auto issue_stage = [&](int kt, int buf) {
        uint32_t base = smb + buf * STAGE_BYTES;
        size_t src0 = (size_t)r0s * 256 + kt * 32 + c0s * 8;
        size_t src1 = (size_t)r1s * 256 + kt * 32 + c0s * 8;
        uint32_t d0 = base + r0s * RS80 + c0s * 16;
        uint32_t d1 = base + r1s * RS80 + c0s * 16;
        cp_async16(d0, aP + src0);
        cp_async16(d1, aP + src1);
        cp_async16(d0 + A_BYTES, bP + src0);
        cp_async16(d1 + A_BYTES, bP + src1);
        CP_COMMIT();
    };

    float acc[2][8][4];
    #pragma unroll
    for (int mi = 0; mi < 2; mi++)
        #pragma unroll
        for (int ni = 0; ni < 8; ni++)
            #pragma unroll
            for (int j = 0; j < 4; j++) acc[mi][ni][j] = 0.f;

    issue_stage(0, 0);
    issue_stage(1, 1);

    int aRowL = warpM * 32 + (lane & 15);
    int aColL = (lane >> 4) * 16;
    int bRowL = (lane & 7) + ((lane >> 4) & 1) * 8;
    int bColL = ((lane >> 3) & 1) * 16;

    for (int kt = 0; kt < 8; kt++) {
        int buf = kt % 3;
        if (kt < 6) { issue_stage(kt + 2, (kt + 2) % 3); CP_WAIT(2); }
        else if (kt == 6) { CP_WAIT(1); }
        else { CP_WAIT(0); }
        __syncthreads();

        uint32_t sbase = smb + buf * STAGE_BYTES;
        #pragma unroll
        for (int kk = 0; kk < 2; kk++) {
            uint32_t af[2][4];
            uint32_t bfr[4][4];
            #pragma unroll
            for (int mi = 0; mi < 2; mi++)
                ldm_x4(af[mi], sbase + (aRowL + mi * 16) * RS80 + kk * 32 + aColL);
            #pragma unroll
            for (int np = 0; np < 4; np++)
                ldm_x4(bfr[np],
                       sbase + A_BYTES + (warpN * 64 + np * 16 + bRowL) * RS80 + kk * 32 + bColL);
            #pragma unroll
            for (int mi = 0; mi < 2; mi++)
                #pragma unroll
                for (int ni = 0; ni < 8; ni++)
                    mma16816(acc[mi][ni], af[mi],
                             bfr[ni >> 1][(ni & 1) * 2], bfr[ni >> 1][(ni & 1) * 2 + 1]);
        }
        __syncthreads();
    }

    #pragma unroll
    for (int mi = 0; mi < 2; mi++) {
        int r0 = rowBase + warpM * 32 + mi * 16 + (lane >> 2);
        #pragma unroll
        for (int ni = 0; ni < 8; ni++) {
            int c = colBase + warpN * 64 + ni * 8 + (lane & 3) * 2;
            float2 v0 = make_float2(acc[mi][ni][0], acc[mi][ni][1]);
            float2 v1 = make_float2(acc[mi][ni][2], acc[mi][ni][3]);
            if (MODE == 2) {
                float* o = (float*)out0v;
                v0.x += bias[c]; v0.y += bias[c + 1];
                v1.x += bias[c]; v1.y += bias[c + 1];
                *(float2*)(o + (size_t)r0 * 256 + c) = v0;
                *(float2*)(o + (size_t)(r0 + 8) * 256 + c) = v1;
            } else {
                int grp = c >> 8;                 // 0 q, 1 k, 2 v
                int cc = c & 255;
                float s = (grp == 0) ? 0.125f : 1.f;
                __half* basep = (grp == 0) ? (__half*)out0v
                              : (grp == 1) ? (__half*)out1v : (__half*)out2v;
                int h = cc >> 6, d0 = cc & 63;
                int b0i = r0 >> 14, n0 = r0 & 16383;
                int b1i = (r0 + 8) >> 14, n1 = (r0 + 8) & 16383;
                __half2 h0 = __floats2half2_rn(v0.x * s, v0.y * s);
                __half2 h1 = __floats2half2_rn(v1.x * s, v1.y * s);
                *(__half2*)(basep + ((size_t)(b0i * 4 + h) * NTOK + n0) * 64 + d0) = h0;
                *(__half2*)(basep + ((size_t)(b1i * 4 + h) * NTOK + n1) * 64 + d0) = h1;
            }
        }
    }
}

// ---------------- tensor-core attention (heads 2,3 + global) -----------------
template <int S, int MODE>
__global__ void __launch_bounds__(256) attn_tc(
    const __half* __restrict__ qg, const __half* __restrict__ kg,
    const __half* __restrict__ vg, const float* __restrict__ gl16,
    __half* __restrict__ fused, int head)
{
    constexpr int P = (S == 256) ? 16 : 8;
    constexpr int NPX = HGT / P;
    constexpr int KV = (S > 128) ? S : 128;
    constexpr int NBLK = (S == 256) ? 4 : 1;

    extern __shared__ char smc[];
    uint32_t smb = smem_u32(smc);
    const uint32_t qOff = 0, kOff = 128 * 128, vOff = kOff + KV * 128;

    int tid = threadIdx.x, warp = tid >> 5, lane = tid & 31;
    int b = blockIdx.x >> 7;
    int gbase = (blockIdx.x & 127) * 128;
    int gkv = (S == 256) ? (gbase & ~255) : gbase;
    size_t hb = (size_t)(b * 4 + head) * NTOK * 64;

    for (int idx = tid; idx < KV * 8; idx += 256) {
        int row = idx >> 3, c = idx & 7;
        int g = gkv + row;
        int win = g / S, pos = g % S;
        int tok = ((win / NPX) * P + pos / P) * HGT + (win % NPX) * P + pos % P;
        const uint4* ks = (const uint4*)(kg + hb + (size_t)tok * 64) + c;
        const uint4* vs = (const uint4*)(vg + hb + (size_t)tok * 64) + c;
        uint32_t so = row * 128 + ((c ^ (row & 7)) << 4);
        *(uint4*)(smc + kOff + so) = *ks;
        *(uint4*)(smc + vOff + so) = *vs;
    }
    for (int idx = tid; idx < 128 * 8; idx += 256) {
        int row = idx >> 3, c = idx & 7;
        uint32_t so = row * 128 + ((c ^ (row & 7)) << 4);
        if (MODE == 0) {
            int g = gbase + row;
            int win = g / S, pos = g % S;
            int tok = ((win / NPX) * P + pos / P) * HGT + (win % NPX) * P + pos % P;
            *(uint4*)(smc + qOff + so) = *((const uint4*)(qg + hb + (size_t)tok * 64) + c);
        } else {
            int pos = (gbase & 255) + row;
            const float* src = gl16 + (size_t)b * 16384 + pos * 64 + c * 8;
            uint32_t hv[4];
            #pragma unroll
            for (int j = 0; j < 4; j++)
                hv[j] = pack_h2(src[2 * j] * SCALE, src[2 * j + 1] * SCALE);
            *(uint4*)(smc + qOff + so) = *(uint4*)hv;
        }
    }
    __syncthreads();

    int qr = warp * 16;
    uint32_t aq[4][4];
    int arow = qr + (lane & 15);
    #pragma unroll
    for (int kk = 0; kk < 4; kk++)
        ldm_x4(aq[kk], smb + qOff + arow * 128 + (((2 * kk + (lane >> 4)) ^ (lane & 7)) << 4));

    float m0 = -1e30f, m1 = -1e30f, l0 = 0.f, l1 = 0.f;
    float acco[8][4];
    #pragma unroll
    for (int ni = 0; ni < 8; ni++)
        #pragma unroll
        for (int j = 0; j < 4; j++) acco[ni][j] = 0.f;

    int kvBase = (S == 256) ? 0 : (warp >> 2) * 64;
    int brow = (lane & 7) + ((lane >> 4) & 1) * 8;
    int bc = (lane >> 3) & 1;

    for (int blk = 0; blk < NBLK; blk++) {
        int tb = kvBase + blk * 64;
        float accs[8][4];
        #pragma unroll
        for (int ni = 0; ni < 8; ni++)
            #pragma unroll
            for (int j = 0; j < 4; j++) accs[ni][j] = 0.f;

        #pragma unroll
        for (int kk = 0; kk < 4; kk++)
            #pragma unroll
            for (int np = 0; np < 4; np++) {
                int krow = tb + np * 16 + brow;
                uint32_t bf[4];
                ldm_x4(bf, smb + kOff + krow * 128 + (((2 * kk + bc) ^ (lane & 7)) << 4));
                mma16816(accs[np * 2],     aq[kk], bf[0], bf[1]);
                mma16816(accs[np * 2 + 1], aq[kk], bf[2], bf[3]);
            }

        float mx0 = -1e30f, mx1 = -1e30f;
        #pragma unroll
        for (int ni = 0; ni < 8; ni++) {
            mx0 = fmaxf(mx0, fmaxf(accs[ni][0], accs[ni][1]));
            mx1 = fmaxf(mx1, fmaxf(accs[ni][2], accs[ni][3]));
        }
        mx0 = fmaxf(mx0, __shfl_xor_sync(0xffffffff, mx0, 1));
        mx0 = fmaxf(mx0, __shfl_xor_sync(0xffffffff, mx0, 2));
        mx1 = fmaxf(mx1, __shfl_xor_sync(0xffffffff, mx1, 1));
        mx1 = fmaxf(mx1, __shfl_xor_sync(0xffffffff, mx1, 2));
        float mn0 = fmaxf(m0, mx0), mn1 = fmaxf(m1, mx1);
        float f0 = __expf(m0 - mn0), f1 = __expf(m1 - mn1);
        m0 = mn0; m1 = mn1;

        float rs0 = 0.f, rs1 = 0.f;
        uint32_t pf[4][4];
        #pragma unroll
        for (int j = 0; j < 4; j++) {
            float p00 = __expf(accs[2 * j][0] - mn0);
            float p01 = __expf(accs[2 * j][1] - mn0);
            float p02 = __expf(accs[2 * j][2] - mn1);
            float p03 = __expf(accs[2 * j][3] - mn1);
            float p10 = __expf(accs[2 * j + 1][0] - mn0);
            float p11 = __expf(accs[2 * j + 1][1] - mn0);
            float p12 = __expf(accs[2 * j + 1][2] - mn1);
            float p13 = __expf(accs[2 * j + 1][3] - mn1);
            rs0 += (p00 + p01) + (p10 + p11);
            rs1 += (p02 + p03) + (p12 + p13);
            pf[j][0] = pack_h2(p00, p01);
            pf[j][1] = pack_h2(p02, p03);
            pf[j][2] = pack_h2(p10, p11);
            pf[j][3] = pack_h2(p12, p13);
        }
        l0 = l0 * f0 + rs0;
        l1 = l1 * f1 + rs1;
        #pragma unroll
        for (int ni = 0; ni < 8; ni++) {
            acco[ni][0] *= f0; acco[ni][1] *= f0;
            acco[ni][2] *= f1; acco[ni][3] *= f1;
        }

        #pragma unroll
        for (int g = 0; g < 4; g++)
            #pragma unroll
            for (int kk = 0; kk < 4; kk++) {
                int vrow = tb + kk * 16 + brow;
                uint32_t bv[4];
                ldm_x4_t(bv, smb + vOff + vrow * 128 + (((2 * g + bc) ^ (lane & 7)) << 4));
                mma16816(acco[2 * g],     pf[kk], bv[0], bv[2]);
                mma16816(acco[2 * g + 1], pf[kk], bv[1], bv[3]);
            }
    }

    l0 += __shfl_xor_sync(0xffffffff, l0, 1);
    l0 += __shfl_xor_sync(0xffffffff, l0, 2);
    l1 += __shfl_xor_sync(0xffffffff, l1, 1);
    l1 += __shfl_xor_sync(0xffffffff, l1, 2);
    float inv0 = 1.f / l0, inv1 = 1.f / l1;

    int grow0 = gbase + qr + (lane >> 2);
    #pragma unroll
    for (int ni = 0; ni < 8; ni++) {
        int col = head * 64 + ni * 8 + (lane & 3) * 2;
        __half2* d0 = (__half2*)(fused + ((size_t)b * NTOK + grow0) * 256 + col);
        __half2* d1 = (__half2*)(fused + ((size_t)b * NTOK + grow0 + 8) * 256 + col);
        float2 v0 = make_float2(acco[ni][0] * inv0, acco[ni][1] * inv0);
        float2 v1 = make_float2(acco[ni][2] * inv1, acco[ni][3] * inv1);
        if (MODE == 1) {
            float2 o0 = __half22float2(*d0), o1 = __half22float2(*d1);
            v0.x += o0.x; v0.y += o0.y;
            v1.x += o1.x; v1.y += o1.y;
        }
        *d0 = __floats2half2_rn(v0.x, v0.y);
        *d1 = __floats2half2_rn(v1.x, v1.y);
    }
}

// ---------------- block-diagonal tensor-core attention (heads 0,1) -----------
// Warp = 16 query rows = one 16-token tile; keys = same 16 tokens.
// Q@K^T m16n16k64 (8 MMAs) -> mask (P=2: 4x4 blocks) -> softmax -> P@V m16n64k16.
template <int P>
__global__ void __launch_bounds__(256) win_tc(
    const __half* __restrict__ qg, const __half* __restrict__ kg,
    const __half* __restrict__ vg, __half* __restrict__ fused, int head)
{
    constexpr int S = P * P;
    constexpr int NPX = HGT / P;

    extern __shared__ char smc[];
    uint32_t smb = smem_u32(smc);
    const uint32_t qOff = 0, kOff = 128 * 128, vOff = 2 * 128 * 128;

    int tid = threadIdx.x, warp = tid >> 5, lane = tid & 31;
    int b = blockIdx.x >> 7;
    int gbase = (blockIdx.x & 127) * 128;
    size_t hb = (size_t)(b * 4 + head) * NTOK * 64;

    // stage Q, K, V: 128 patch-ordered tokens each (swizzled fp16)
    for (int idx = tid; idx < 128 * 8; idx += 256) {
        int row = idx >> 3, c = idx & 7;
        int g = gbase + row;
        int win = g / S, pos = g % S;
        int tok = ((win / NPX) * P + pos / P) * HGT + (win % NPX) * P + pos % P;
        uint32_t so = row * 128 + ((c ^ (row & 7)) << 4);
        *(uint4*)(smc + qOff + so) = *((const uint4*)(qg + hb + (size_t)tok * 64) + c);
        *(uint4*)(smc + kOff + so) = *((const uint4*)(kg + hb + (size_t)tok * 64) + c);
        *(uint4*)(smc + vOff + so) = *((const uint4*)(vg + hb + (size_t)tok * 64) + c);
    }
    __syncthreads();

    int qr = warp * 16;
    uint32_t aq[4][4];
    int arow = qr + (lane & 15);
    #pragma unroll
    for (int kk = 0; kk < 4; kk++)
        ldm_x4(aq[kk], smb + qOff + arow * 128 + (((2 * kk + (lane >> 4)) ^ (lane & 7)) << 4));

    int brow = (lane & 7) + ((lane >> 4) & 1) * 8;
    int bc = (lane >> 3) & 1;

    // S = Q @ K^T over the warp's own 16-token tile
    float accs[2][4];
    #pragma unroll
    for (int ni = 0; ni < 2; ni++)
        #pragma unroll
        for (int j = 0; j < 4; j++) accs[ni][j] = 0.f;
    #pragma unroll
    for (int kk = 0; kk < 4; kk++) {
        uint32_t bf[4];
        ldm_x4(bf, smb + kOff + (qr + brow) * 128 + (((2 * kk + bc) ^ (lane & 7)) << 4));
        mma16816(accs[0], aq[kk], bf[0], bf[1]);
        mma16816(accs[1], aq[kk], bf[2], bf[3]);
    }

    // block-diagonal mask (only needed when window S < 16, i.e. P=2)
    if (S < 16) {
        int r0 = lane >> 2;
        #pragma unroll
        for (int ni = 0; ni < 2; ni++)
            #pragma unroll
            for (int j = 0; j < 4; j++) {
                int row = r0 + ((j >> 1) << 3);
                int col = ni * 8 + (lane & 3) * 2 + (j & 1);
                if ((row / S) != (col / S)) accs[ni][j] = -1e30f;
            }
    }

    // softmax over 16 cols (rows r0 and r0+8)
    float mx0 = fmaxf(fmaxf(accs[0][0], accs[0][1]), fmaxf(accs[1][0], accs[1][1]));
    float mx1 = fmaxf(fmaxf(accs[0][2], accs[0][3]), fmaxf(accs[1][2], accs[1][3]));
    mx0 = fmaxf(mx0, __shfl_xor_sync(0xffffffff, mx0, 1));
    mx0 = fmaxf(mx0, __shfl_xor_sync(0xffffffff, mx0, 2));
    mx1 = fmaxf(mx1, __shfl_xor_sync(0xffffffff, mx1, 1));
    mx1 = fmaxf(mx1, __shfl_xor_sync(0xffffffff, mx1, 2));

    float p00 = __expf(accs[0][0] - mx0);
    float p01 = __expf(accs[0][1] - mx0);
    float p02 = __expf(accs[0][2] - mx1);
    float p03 = __expf(accs[0][3] - mx1);
    float p10 = __expf(accs[1][0] - mx0);
    float p11 = __expf(accs[1][1] - mx0);
    float p12 = __expf(accs[1][2] - mx1);
    float p13 = __expf(accs[1][3] - mx1);
    float l0 = (p00 + p01) + (p10 + p11);
    float l1 = (p02 + p03) + (p12 + p13);
    l0 += __shfl_xor_sync(0xffffffff, l0, 1);
    l0 += __shfl_xor_sync(0xffffffff, l0, 2);
    l1 += __shfl_xor_sync(0xffffffff, l1, 1);
    l1 += __shfl_xor_sync(0xffffffff, l1, 2);

    uint32_t pf[4];
    pf[0] = pack_h2(p00, p01);
    pf[1] = pack_h2(p02, p03);
    pf[2] = pack_h2(p10, p11);
    pf[3] = pack_h2(p12, p13);

    // O = P @ V (k=16, n=64)
    float acco[8][4];
    #pragma unroll
    for (int ni = 0; ni < 8; ni++)
        #pragma unroll
        for (int j = 0; j < 4; j++) acco[ni][j] = 0.f;
    #pragma unroll
    for (int g = 0; g < 4; g++) {
        uint32_t bv[4];
        ldm_x4_t(bv, smb + vOff + (qr + brow) * 128 + (((2 * g + bc) ^ (lane & 7)) << 4));
        mma16816(acco[2 * g],     pf, bv[0], bv[2]);
        mma16816(acco[2 * g + 1], pf, bv[1], bv[3]);
    }

    float inv0 = 1.f / l0, inv1 = 1.f / l1;
    int grow0 = gbase + qr + (lane >> 2);
    #pragma unroll
    for (int ni = 0; ni < 8; ni++) {
        int col = head * 64 + ni * 8 + (lane & 3) * 2;
        __half2* d0 = (__half2*)(fused + ((size_t)b * NTOK + grow0) * 256 + col);
        __half2* d1 = (__half2*)(fused + ((size_t)b * NTOK + grow0 + 8) * 256 + col);
        *d0 = __floats2half2_rn(acco[ni][0] * inv0, acco[ni][1] * inv0);
        *d1 = __floats2half2_rn(acco[ni][2] * inv1, acco[ni][3] * inv1);
    }
}

// ---------------- block-parallel window mean + bilinear upsample -------------
template <int P>
__global__ void __launch_bounds__(512) mean_red(
    const __half* __restrict__ fused, const float* __restrict__ glp,
    float* __restrict__ glo, int head)
{
    constexpr int S = P * P, NP = (HGT / P) * (HGT / P);
    __shared__ float red[8][64];

    int d = threadIdx.x;
    int wt = threadIdx.y;
    int blk = blockIdx.x;
    int b = blk / (P * P);
    int pos = blk % (P * P);
    int iy = pos / P, ix = pos % P;

    const __half* fp = fused + (size_t)b * NTOK * 256 + (size_t)pos * 256 + head * 64 + d;
    float s = 0.f;
    for (int w = wt; w < NP; w += 8) s += __half2float(fp[(size_t)w * S * 256]);
    red[wt][d] = s;
    __syncthreads();

    if (wt == 0) {
        float tot = red[0][d];
        #pragma unroll
        for (int j = 1; j < 8; j++) tot += red[j][d];
        float val = tot * (1.f / NP);

        if (glp) {
            int Pp = P / 2;
            float sy = (iy + 0.5f) * 0.5f - 0.5f;
            float sx = (ix + 0.5f) * 0.5f - 0.5f;
            float fy = floorf(sy), fx = floorf(sx);
            float wy = sy - fy, wx = sx - fx;
            int y0 = (int)fy, x0 = (int)fx;
            int y0c = max(0, min(Pp - 1, y0)), y1c = max(0, min(Pp - 1, y0 + 1));
            int x0c = max(0, min(Pp - 1, x0)), x1c = max(0, min(Pp - 1, x0 + 1));
            const float* gp = glp + (size_t)(b * 64 + d) * Pp * Pp;
            float v = (1.f - wy) * ((1.f - wx) * gp[y0c * Pp + x0c] + wx * gp[y0c * Pp + x1c])
                    + wy * ((1.f - wx) * gp[y1c * Pp + x0c] + wx * gp[y1c * Pp + x1c]);
            val += v;
        }
        glo[((size_t)(b * 64 + d) * P + iy) * P + ix] = val;
    }
}

// ---------------- launch ------------------------------------------------------
extern "C" void kernel_launch(void* const* d_in, const int* in_sizes, int n_in,
                              void* d_out, int out_size)
{
    (void)in_sizes; (void)n_in; (void)out_size;
    const float* x     = (const float*)d_in[0];
    const float* Wq    = (const float*)d_in[1];
    const float* Wkv   = (const float*)d_in[2];
    const float* Wproj = (const float*)d_in[3];
    const float* bproj = (const float*)d_in[4];
    float* out = (float*)d_out;

    float *gl0, *gl1, *gl2, *gl3;
    __half *qh, *kh, *vh, *fh, *xh, *wqkv, *wp;
    cudaGetSymbolAddress((void**)&qh, g_qh);
    cudaGetSymbolAddress((void**)&kh, g_kh);
    cudaGetSymbolAddress((void**)&vh, g_vh);
    cudaGetSymbolAddress((void**)&fh, g_fh);
    cudaGetSymbolAddress((void**)&gl0, g_gl0);
    cudaGetSymbolAddress((void**)&gl1, g_gl1);
    cudaGetSymbolAddress((void**)&gl2, g_gl2);
    cudaGetSymbolAddress((void**)&gl3, g_gl3);
    cudaGetSymbolAddress((void**)&xh, g_xh);
    cudaGetSymbolAddress((void**)&wqkv, g_wqkv);
    cudaGetSymbolAddress((void**)&wp, g_wp);

    cudaFuncSetAttribute(gemm_mma<0>, cudaFuncAttributeMaxDynamicSharedMemorySize, GEMM_SMEM);
    cudaFuncSetAttribute(gemm_mma<2>, cudaFuncAttributeMaxDynamicSharedMemorySize, GEMM_SMEM);
    cudaFuncSetAttribute((win_tc<2>),  cudaFuncAttributeMaxDynamicSharedMemorySize, 49152);
    cudaFuncSetAttribute((win_tc<4>),  cudaFuncAttributeMaxDynamicSharedMemorySize, 49152);
    cudaFuncSetAttribute((attn_tc<64, 0>),  cudaFuncAttributeMaxDynamicSharedMemorySize, 49152);
    cudaFuncSetAttribute((attn_tc<256, 0>), cudaFuncAttributeMaxDynamicSharedMemorySize, 81920);
    cudaFuncSetAttribute((attn_tc<256, 1>), cudaFuncAttributeMaxDynamicSharedMemorySize, 81920);

    // 1: weights, 2: input convert, 3: fused QKV projection
    wsplit_all<<<1024, 256>>>(Wq, Wkv, Wproj, wqkv, wp);
    conv_fp16<<<(MTOT * 256 / 4 + 255) / 256, 256>>>(x, xh, MTOT * 256 / 4);
    gemm_mma<0><<<dim3(6, 1024), 256, GEMM_SMEM>>>(xh, wqkv, qh, kh, vh, nullptr);

    // 4 (ncu-profiled slot): block-diagonal tensor-core win_tc<2>
    win_tc<2><<<1024, 256, 49152>>>(qh, kh, vh, fh, 0);
    win_tc<4><<<1024, 256, 49152>>>(qh, kh, vh, fh, 1);
    attn_tc<64, 0> <<<1024, 256, 49152>>>(qh, kh, vh, nullptr, fh, 2);
    attn_tc<256, 0><<<1024, 256, 81920>>>(qh, kh, vh, nullptr, fh, 3);

    // hierarchical global feature (block-parallel reductions)
    mean_red<2> <<<BATCH * 4,   dim3(64, 8)>>>(fh, nullptr, gl0, 0);
    mean_red<4> <<<BATCH * 16,  dim3(64, 8)>>>(fh, gl0, gl1, 1);
    mean_red<8> <<<BATCH * 64,  dim3(64, 8)>>>(fh, gl1, gl2, 2);
    mean_red<16><<<BATCH * 256, dim3(64, 8)>>>(fh, gl2, gl3, 3);

    // global attention on head 3 (tensor cores, adds into fused)
    attn_tc<256, 1><<<1024, 256, 81920>>>(qh, kh, vh, gl3, fh, 3);

    // output projection (reads fp16 fused directly)
    gemm_mma<2><<<dim3(2, 1024), 256, GEMM_SMEM>>>(fh, wp, out, nullptr, nullptr, bproj);
}